// round 11
// baseline (speedup 1.0000x reference)
#include <cuda_runtime.h>
#include <cuda_fp16.h>

#define N_MAX 100000
#define E_MAX 1600000
#define IN_CH 128
#define HID 64
#define OUT 32

// ---- scratch (device globals: allocation-free rule) ----
__device__ __align__(16) __half g_h1s[(size_t)N_MAX * HID];   // dis-scaled xW1, fp16
__device__ __align__(16) __half g_h2s[(size_t)N_MAX * OUT];   // dis-scaled hW2, fp16
__device__ int   g_cnt[N_MAX];
__device__ int   g_offs[N_MAX + 1];
__device__ int   g_cursor[N_MAX];
__device__ int   g_csr[E_MAX];
__device__ float g_dis[N_MAX];
__device__ int   g_local[N_MAX];
__device__ int   g_bsum[1024];

#define SCAN_B 256

// ---- packed fp32x2 helpers (sm_100+) ----
__device__ __forceinline__ unsigned long long pack2(float x) {
    unsigned long long r;
    asm("mov.b64 %0, {%1, %1};" : "=l"(r) : "r"(__float_as_uint(x)));
    return r;
}
__device__ __forceinline__ unsigned long long fma2(unsigned long long a, unsigned long long b,
                                                   unsigned long long c) {
    unsigned long long d;
    asm("fma.rn.f32x2 %0, %1, %2, %3;" : "=l"(d) : "l"(a), "l"(b), "l"(c));
    return d;
}
__device__ __forceinline__ float lo32(unsigned long long v) {
    return __uint_as_float((unsigned)(v & 0xffffffffull));
}
__device__ __forceinline__ float hi32(unsigned long long v) {
    return __uint_as_float((unsigned)(v >> 32));
}

// ---------------------------------------------------------------- count in-degree
__global__ void count_kernel(const int* __restrict__ ei, int E) {
    int e = blockIdx.x * blockDim.x + threadIdx.x;
    if (e < E) atomicAdd(&g_cnt[ei[E + e]], 1);
}

// ---------------------------------------------------------------- scan stage 1: per-block scan
__global__ void scan1_kernel(int N) {
    __shared__ int sm[SCAN_B];
    int b = blockIdx.x, t = threadIdx.x;
    int i = b * SCAN_B + t;
    int v = (i < N) ? g_cnt[i] : 0;
    sm[t] = v; __syncthreads();
    for (int off = 1; off < SCAN_B; off <<= 1) {
        int add = (t >= off) ? sm[t - off] : 0;
        __syncthreads();
        sm[t] += add;
        __syncthreads();
    }
    if (i < N) g_local[i] = sm[t] - v;
    if (t == SCAN_B - 1) g_bsum[b] = sm[t];
}

// ---------------------------------------------------------------- scan stage 2+3 fused:
// block b reduces bsum[0..b-1] itself (<=391 ints), then finalizes offs/cursor/dis.
__global__ void scan23_kernel(int N, int E) {
    int b = blockIdx.x, t = threadIdx.x;
    int sum = 0;
    for (int j = t; j < b; j += SCAN_B) sum += g_bsum[j];
    // block reduce
    #pragma unroll
    for (int o = 16; o > 0; o >>= 1) sum += __shfl_down_sync(0xffffffffu, sum, o);
    __shared__ int ws[SCAN_B / 32];
    if ((t & 31) == 0) ws[t >> 5] = sum;
    __syncthreads();
    if (t < SCAN_B / 32) {
        int v = ws[t];
        #pragma unroll
        for (int o = SCAN_B / 64; o > 0; o >>= 1) v += __shfl_down_sync(0xffu, v, o);
        if (t == 0) ws[0] = v;
    }
    __syncthreads();
    int bpre = ws[0];
    int i = b * SCAN_B + t;
    if (i < N) {
        int o = g_local[i] + bpre;
        g_offs[i] = o;
        g_cursor[i] = o;
        g_dis[i] = rsqrtf((float)(g_cnt[i] + 1));   // +1 self loop
    }
    if (b == 0 && t == 0) g_offs[N] = E;
}

// ---------------------------------------------------------------- CSR scatter
__global__ void scatter_kernel(const int* __restrict__ ei, int E) {
    int e = blockIdx.x * blockDim.x + threadIdx.x;
    if (e < E) {
        int dst = ei[E + e];
        int pos = atomicAdd(&g_cursor[dst], 1);
        g_csr[pos] = ei[e];
    }
}

// ---------------------------------------------------------------- GEMM1: h1s = fp16(dis * (x @ W1))  [f32x2]
#define G1_NODES 64
#define XS 132
__global__ void gemm1_kernel(const float* __restrict__ x, const float* __restrict__ W1,
                             __half* __restrict__ h1s, int N) {
    extern __shared__ float sm[];
    float* Ws = sm;                  // 128*64
    float* Xs = sm + IN_CH * HID;    // 64*132
    int t = threadIdx.x;
    int nodeBase = blockIdx.x * G1_NODES;

    for (int i = t; i < IN_CH * HID / 4; i += 256)
        ((float4*)Ws)[i] = ((const float4*)W1)[i];
    for (int i = t; i < G1_NODES * IN_CH / 4; i += 256) {
        int n  = i / (IN_CH / 4);
        int c4 = i % (IN_CH / 4);
        int gn = nodeBase + n;
        float4 v = make_float4(0.f, 0.f, 0.f, 0.f);
        if (gn < N) v = ((const float4*)(x + (size_t)gn * IN_CH))[c4];
        *(float4*)(Xs + n * XS + c4 * 4) = v;
    }
    __syncthreads();

    int ch0 = (t & 15) * 4;
    int n0  = (t >> 4) * 4;
    unsigned long long a01[4] = {0ull, 0ull, 0ull, 0ull};
    unsigned long long a23[4] = {0ull, 0ull, 0ull, 0ull};
    #pragma unroll 4
    for (int k = 0; k < IN_CH; k += 4) {
        float4 xv[4];
        #pragma unroll
        for (int j = 0; j < 4; j++) xv[j] = *(float4*)(Xs + (n0 + j) * XS + k);
        #pragma unroll
        for (int kk = 0; kk < 4; kk++) {
            ulonglong2 wv = *(const ulonglong2*)(Ws + (k + kk) * HID + ch0);
            #pragma unroll
            for (int j = 0; j < 4; j++) {
                float xs = (kk == 0) ? xv[j].x : (kk == 1) ? xv[j].y : (kk == 2) ? xv[j].z : xv[j].w;
                unsigned long long xx = pack2(xs);
                a01[j] = fma2(xx, wv.x, a01[j]);
                a23[j] = fma2(xx, wv.y, a23[j]);
            }
        }
    }
    #pragma unroll
    for (int j = 0; j < 4; j++) {
        int gn = nodeBase + n0 + j;
        if (gn < N) {
            float dis = g_dis[gn];
            __half2 o0 = __floats2half2_rn(lo32(a01[j]) * dis, hi32(a01[j]) * dis);
            __half2 o1 = __floats2half2_rn(lo32(a23[j]) * dis, hi32(a23[j]) * dis);
            *(__half2*)(h1s + (size_t)gn * HID + ch0)     = o0;
            *(__half2*)(h1s + (size_t)gn * HID + ch0 + 2) = o1;
        }
    }
}

// ---------------------------------------------------------------- fused agg1 + relu + bias + GEMM2
#define L2_NODES 64
#define HS 68
__global__ void layer12_kernel(const __half* __restrict__ h1s,
                               const float* __restrict__ b1, const float* __restrict__ W2,
                               __half* __restrict__ h2s, int N) {
    __shared__ __align__(16) float Ws[HID * OUT];       // 8 KB
    __shared__ __align__(16) float Hs[L2_NODES * HS];   // ~17.4 KB
    __shared__ float Dis[L2_NODES];
    int t = threadIdx.x;
    int warp = t >> 5, lane = t & 31;
    int nodeBase = blockIdx.x * L2_NODES;

    for (int i = t; i < HID * OUT / 4; i += 256)
        ((float4*)Ws)[i] = ((const float4*)W2)[i];

    float2 bb;
    bb.x = b1[lane * 2];
    bb.y = b1[lane * 2 + 1];

    #pragma unroll 1
    for (int j = 0; j < 8; j++) {
        int n  = warp * 8 + j;
        int gn = nodeBase + n;
        float2 acc = make_float2(0.f, 0.f);
        float d = 0.f;
        if (gn < N) {
            d = g_dis[gn];
            int beg = g_offs[gn], end = g_offs[gn + 1];
            for (int e = beg; e < end; e += 32) {
                int cnt = min(32, end - e);
                int s = (lane < cnt) ? g_csr[e + lane] : 0;
                int k = 0;
                for (; k + 4 <= cnt; k += 4) {
                    int s0 = __shfl_sync(0xffffffffu, s, k);
                    int s1 = __shfl_sync(0xffffffffu, s, k + 1);
                    int s2 = __shfl_sync(0xffffffffu, s, k + 2);
                    int s3 = __shfl_sync(0xffffffffu, s, k + 3);
                    float2 v0 = __half22float2(__ldg((const __half2*)(h1s + (size_t)s0 * HID + lane * 2)));
                    float2 v1 = __half22float2(__ldg((const __half2*)(h1s + (size_t)s1 * HID + lane * 2)));
                    float2 v2 = __half22float2(__ldg((const __half2*)(h1s + (size_t)s2 * HID + lane * 2)));
                    float2 v3 = __half22float2(__ldg((const __half2*)(h1s + (size_t)s3 * HID + lane * 2)));
                    acc.x += v0.x + v1.x; acc.y += v0.y + v1.y;
                    acc.x += v2.x + v3.x; acc.y += v2.y + v3.y;
                }
                for (; k < cnt; k++) {
                    int ss = __shfl_sync(0xffffffffu, s, k);
                    float2 v = __half22float2(__ldg((const __half2*)(h1s + (size_t)ss * HID + lane * 2)));
                    acc.x += v.x; acc.y += v.y;
                }
            }
            // self loop
            float2 sv = __half22float2(*(const __half2*)(h1s + (size_t)gn * HID + lane * 2));
            acc.x += sv.x; acc.y += sv.y;
            acc.x = fmaxf(fmaf(d, acc.x, bb.x), 0.f);
            acc.y = fmaxf(fmaf(d, acc.y, bb.y), 0.f);
        }
        *(float2*)(Hs + n * HS + lane * 2) = acc;
        if (lane == 0) Dis[n] = d;
    }
    __syncthreads();

    // GEMM: 64x32 = Hs(64x64) @ Ws(64x32); thread = 2 nodes x 4 ch, f32x2 packed
    int ch0 = (t & 7) * 4;
    int n0  = (t >> 3) * 2;
    unsigned long long a01[2] = {0ull, 0ull};
    unsigned long long a23[2] = {0ull, 0ull};
    #pragma unroll 4
    for (int k = 0; k < HID; k += 4) {
        float4 xv[2];
        #pragma unroll
        for (int j = 0; j < 2; j++) xv[j] = *(float4*)(Hs + (n0 + j) * HS + k);
        #pragma unroll
        for (int kk = 0; kk < 4; kk++) {
            ulonglong2 wv = *(const ulonglong2*)(Ws + (k + kk) * OUT + ch0);
            #pragma unroll
            for (int j = 0; j < 2; j++) {
                float xs = (kk == 0) ? xv[j].x : (kk == 1) ? xv[j].y : (kk == 2) ? xv[j].z : xv[j].w;
                unsigned long long xx = pack2(xs);
                a01[j] = fma2(xx, wv.x, a01[j]);
                a23[j] = fma2(xx, wv.y, a23[j]);
            }
        }
    }
    #pragma unroll
    for (int j = 0; j < 2; j++) {
        int gn = nodeBase + n0 + j;
        if (gn < N) {
            float d = Dis[n0 + j];
            __half2 o0 = __floats2half2_rn(lo32(a01[j]) * d, hi32(a01[j]) * d);
            __half2 o1 = __floats2half2_rn(lo32(a23[j]) * d, hi32(a23[j]) * d);
            *(__half2*)(h2s + (size_t)gn * OUT + ch0)     = o0;
            *(__half2*)(h2s + (size_t)gn * OUT + ch0 + 2) = o1;
        }
    }
}

// ---------------------------------------------------------------- fused agg2 + scale + bias -> out
__global__ void agg2_final_kernel(const __half* __restrict__ h2s,
                                  const float* __restrict__ b2,
                                  float* __restrict__ out, int N) {
    int w = (blockIdx.x * blockDim.x + threadIdx.x) >> 5;
    int lane = threadIdx.x & 31;
    if (w >= N) return;
    float acc = 0.f;
    int beg = g_offs[w], end = g_offs[w + 1];
    for (int e = beg; e < end; e += 32) {
        int cnt = min(32, end - e);
        int s = (lane < cnt) ? g_csr[e + lane] : 0;
        int k = 0;
        for (; k + 4 <= cnt; k += 4) {
            int s0 = __shfl_sync(0xffffffffu, s, k);
            int s1 = __shfl_sync(0xffffffffu, s, k + 1);
            int s2 = __shfl_sync(0xffffffffu, s, k + 2);
            int s3 = __shfl_sync(0xffffffffu, s, k + 3);
            float v0 = __half2float(__ldg(h2s + (size_t)s0 * OUT + lane));
            float v1 = __half2float(__ldg(h2s + (size_t)s1 * OUT + lane));
            float v2 = __half2float(__ldg(h2s + (size_t)s2 * OUT + lane));
            float v3 = __half2float(__ldg(h2s + (size_t)s3 * OUT + lane));
            acc += (v0 + v1) + (v2 + v3);
        }
        for (; k < cnt; k++) {
            int ss = __shfl_sync(0xffffffffu, s, k);
            acc += __half2float(__ldg(h2s + (size_t)ss * OUT + lane));
        }
    }
    acc += __half2float(h2s[(size_t)w * OUT + lane]);   // self loop
    out[(size_t)w * OUT + lane] = fmaf(g_dis[w], acc, b2[lane]);
}

// ---------------------------------------------------------------- launch
extern "C" void kernel_launch(void* const* d_in, const int* in_sizes, int n_in,
                              void* d_out, int out_size) {
    const float* x  = (const float*)d_in[0];
    const int*   ei = (const int*)d_in[1];
    const float* W1 = (const float*)d_in[2];
    const float* b1 = (const float*)d_in[3];
    const float* W2 = (const float*)d_in[4];
    const float* b2 = (const float*)d_in[5];
    float* out = (float*)d_out;

    int N = in_sizes[0] / IN_CH;
    int E = in_sizes[1] / 2;

    __half *h1s, *h2s;
    int* cnt_ptr;
    cudaGetSymbolAddress((void**)&h1s, g_h1s);
    cudaGetSymbolAddress((void**)&h2s, g_h2s);
    cudaGetSymbolAddress((void**)&cnt_ptr, g_cnt);

    const int gemm1_smem = (IN_CH * HID + G1_NODES * XS) * (int)sizeof(float);

    // one-time host-side resources (created on first, uncaptured, correctness call)
    static cudaStream_t s2 = nullptr;
    static cudaEvent_t evF = nullptr, evJ = nullptr;
    if (s2 == nullptr) {
        cudaStreamCreateWithFlags(&s2, cudaStreamNonBlocking);
        cudaEventCreateWithFlags(&evF, cudaEventDisableTiming);
        cudaEventCreateWithFlags(&evJ, cudaEventDisableTiming);
        cudaFuncSetAttribute(gemm1_kernel, cudaFuncAttributeMaxDynamicSharedMemorySize, gemm1_smem);
    }

    int B = (N + SCAN_B - 1) / SCAN_B;

    // main: degree + offsets (produces cursor + dis)
    cudaMemsetAsync(cnt_ptr, 0, (size_t)N * sizeof(int), 0);
    count_kernel<<<(E + 255) / 256, 256>>>(ei, E);
    scan1_kernel<<<B, SCAN_B>>>(N);
    scan23_kernel<<<B, SCAN_B>>>(N, E);

    // fork: scatter (needs cursor) on side stream, gemm1 (needs dis) on main
    cudaEventRecord(evF, 0);
    cudaStreamWaitEvent(s2, evF, 0);
    scatter_kernel<<<(E + 255) / 256, 256, 0, s2>>>(ei, E);
    cudaEventRecord(evJ, s2);

    gemm1_kernel<<<(N + G1_NODES - 1) / G1_NODES, 256, gemm1_smem>>>(x, W1, h1s, N);

    // join: layer12 needs h1s (main) + csr (side)
    cudaStreamWaitEvent(0, evJ, 0);
    layer12_kernel<<<(N + L2_NODES - 1) / L2_NODES, 256>>>(h1s, b1, W2, h2s, N);
    agg2_final_kernel<<<(N * 32 + 255) / 256, 256>>>(h2s, b2, out, N);
}

// round 12
// speedup vs baseline: 1.0557x; 1.0557x over previous
#include <cuda_runtime.h>
#include <cuda_fp16.h>

#define N_MAX 100000
#define E_MAX 1600000
#define IN_CH 128
#define HID 64
#define OUT 32

// ---- scratch (device globals: allocation-free rule) ----
__device__ __align__(16) __half g_h1s[(size_t)N_MAX * HID];   // xW1 (unscaled, then scaled in-place)
__device__ __align__(16) __half g_h2s[(size_t)N_MAX * OUT];   // dis-scaled hW2, fp16
__device__ int   g_cnt[N_MAX];
__device__ int   g_offs[N_MAX + 1];
__device__ int   g_cursor[N_MAX];
__device__ int   g_csr[E_MAX];
__device__ float g_dis[N_MAX];
__device__ int   g_local[N_MAX];
__device__ int   g_bsum[1024];

#define SCAN_B 256

// ---- packed fp32x2 helpers (sm_100+) ----
__device__ __forceinline__ unsigned long long pack2(float x) {
    unsigned long long r;
    asm("mov.b64 %0, {%1, %1};" : "=l"(r) : "r"(__float_as_uint(x)));
    return r;
}
__device__ __forceinline__ unsigned long long fma2(unsigned long long a, unsigned long long b,
                                                   unsigned long long c) {
    unsigned long long d;
    asm("fma.rn.f32x2 %0, %1, %2, %3;" : "=l"(d) : "l"(a), "l"(b), "l"(c));
    return d;
}
__device__ __forceinline__ float lo32(unsigned long long v) {
    return __uint_as_float((unsigned)(v & 0xffffffffull));
}
__device__ __forceinline__ float hi32(unsigned long long v) {
    return __uint_as_float((unsigned)(v >> 32));
}

// ---------------------------------------------------------------- count in-degree (x4 vectorized)
__global__ void count_kernel(const int* __restrict__ ei, int E) {
    int i = blockIdx.x * blockDim.x + threadIdx.x;
    int E4 = E >> 2;
    if (i < E4) {
        int4 d = ((const int4*)(ei + E))[i];
        atomicAdd(&g_cnt[d.x], 1);
        atomicAdd(&g_cnt[d.y], 1);
        atomicAdd(&g_cnt[d.z], 1);
        atomicAdd(&g_cnt[d.w], 1);
    }
    // tail
    int tail = E4 * 4 + i;
    if (i < (E & 3) && tail < E) atomicAdd(&g_cnt[ei[E + tail]], 1);
}

// ---------------------------------------------------------------- scan stage 1: per-block scan
__global__ void scan1_kernel(int N) {
    __shared__ int sm[SCAN_B];
    int b = blockIdx.x, t = threadIdx.x;
    int i = b * SCAN_B + t;
    int v = (i < N) ? g_cnt[i] : 0;
    sm[t] = v; __syncthreads();
    for (int off = 1; off < SCAN_B; off <<= 1) {
        int add = (t >= off) ? sm[t - off] : 0;
        __syncthreads();
        sm[t] += add;
        __syncthreads();
    }
    if (i < N) g_local[i] = sm[t] - v;
    if (t == SCAN_B - 1) g_bsum[b] = sm[t];
}

// ---------------------------------------------------------------- scan stage 2+3 fused
__global__ void scan23_kernel(int N, int E) {
    int b = blockIdx.x, t = threadIdx.x;
    int sum = 0;
    for (int j = t; j < b; j += SCAN_B) sum += g_bsum[j];
    #pragma unroll
    for (int o = 16; o > 0; o >>= 1) sum += __shfl_down_sync(0xffffffffu, sum, o);
    __shared__ int ws[SCAN_B / 32];
    if ((t & 31) == 0) ws[t >> 5] = sum;
    __syncthreads();
    if (t < SCAN_B / 32) {
        int v = ws[t];
        #pragma unroll
        for (int o = SCAN_B / 64; o > 0; o >>= 1) v += __shfl_down_sync(0xffu, v, o);
        if (t == 0) ws[0] = v;
    }
    __syncthreads();
    int bpre = ws[0];
    int i = b * SCAN_B + t;
    if (i < N) {
        int o = g_local[i] + bpre;
        g_offs[i] = o;
        g_cursor[i] = o;
        g_dis[i] = rsqrtf((float)(g_cnt[i] + 1));   // +1 self loop
    }
    if (b == 0 && t == 0) g_offs[N] = E;
}

// ---------------------------------------------------------------- CSR scatter (x4 vectorized)
__global__ void scatter_kernel(const int* __restrict__ ei, int E) {
    int i = blockIdx.x * blockDim.x + threadIdx.x;
    int E4 = E >> 2;
    if (i < E4) {
        int4 s = ((const int4*)ei)[i];
        int4 d = ((const int4*)(ei + E))[i];
        int p0 = atomicAdd(&g_cursor[d.x], 1);
        int p1 = atomicAdd(&g_cursor[d.y], 1);
        int p2 = atomicAdd(&g_cursor[d.z], 1);
        int p3 = atomicAdd(&g_cursor[d.w], 1);
        g_csr[p0] = s.x;
        g_csr[p1] = s.y;
        g_csr[p2] = s.z;
        g_csr[p3] = s.w;
    }
    int tail = E4 * 4 + i;
    if (i < (E & 3) && tail < E) {
        int pos = atomicAdd(&g_cursor[ei[E + tail]], 1);
        g_csr[pos] = ei[tail];
    }
}

// ---------------------------------------------------------------- GEMM1: h1s = fp16(x @ W1)  [unscaled, f32x2]
#define G1_NODES 64
#define XS 132
__global__ void gemm1_kernel(const float* __restrict__ x, const float* __restrict__ W1,
                             __half* __restrict__ h1s, int N) {
    extern __shared__ float sm[];
    float* Ws = sm;                  // 128*64
    float* Xs = sm + IN_CH * HID;    // 64*132
    int t = threadIdx.x;
    int nodeBase = blockIdx.x * G1_NODES;

    for (int i = t; i < IN_CH * HID / 4; i += 256)
        ((float4*)Ws)[i] = ((const float4*)W1)[i];
    for (int i = t; i < G1_NODES * IN_CH / 4; i += 256) {
        int n  = i / (IN_CH / 4);
        int c4 = i % (IN_CH / 4);
        int gn = nodeBase + n;
        float4 v = make_float4(0.f, 0.f, 0.f, 0.f);
        if (gn < N) v = ((const float4*)(x + (size_t)gn * IN_CH))[c4];
        *(float4*)(Xs + n * XS + c4 * 4) = v;
    }
    __syncthreads();

    int ch0 = (t & 15) * 4;
    int n0  = (t >> 4) * 4;
    unsigned long long a01[4] = {0ull, 0ull, 0ull, 0ull};
    unsigned long long a23[4] = {0ull, 0ull, 0ull, 0ull};
    #pragma unroll 4
    for (int k = 0; k < IN_CH; k += 4) {
        float4 xv[4];
        #pragma unroll
        for (int j = 0; j < 4; j++) xv[j] = *(float4*)(Xs + (n0 + j) * XS + k);
        #pragma unroll
        for (int kk = 0; kk < 4; kk++) {
            ulonglong2 wv = *(const ulonglong2*)(Ws + (k + kk) * HID + ch0);
            #pragma unroll
            for (int j = 0; j < 4; j++) {
                float xs = (kk == 0) ? xv[j].x : (kk == 1) ? xv[j].y : (kk == 2) ? xv[j].z : xv[j].w;
                unsigned long long xx = pack2(xs);
                a01[j] = fma2(xx, wv.x, a01[j]);
                a23[j] = fma2(xx, wv.y, a23[j]);
            }
        }
    }
    #pragma unroll
    for (int j = 0; j < 4; j++) {
        int gn = nodeBase + n0 + j;
        if (gn < N) {
            __half2 o0 = __floats2half2_rn(lo32(a01[j]), hi32(a01[j]));
            __half2 o1 = __floats2half2_rn(lo32(a23[j]), hi32(a23[j]));
            *(__half2*)(h1s + (size_t)gn * HID + ch0)     = o0;
            *(__half2*)(h1s + (size_t)gn * HID + ch0 + 2) = o1;
        }
    }
}

// ---------------------------------------------------------------- scale h1s *= dis[node]
__global__ void scale_h1_kernel(__half* __restrict__ h1s, int N) {
    int i = blockIdx.x * blockDim.x + threadIdx.x;
    int total = N * (HID / 8);
    if (i >= total) return;
    int n = i >> 3;
    float d = g_dis[n];
    uint4 v = ((const uint4*)h1s)[i];
    __half2* h = (__half2*)&v;
    #pragma unroll
    for (int j = 0; j < 4; j++) {
        float2 f = __half22float2(h[j]);
        h[j] = __floats2half2_rn(f.x * d, f.y * d);
    }
    ((uint4*)h1s)[i] = v;
}

// ---------------------------------------------------------------- fused agg1 + relu + bias + GEMM2
#define L2_NODES 64
#define HS 68
__global__ void layer12_kernel(const __half* __restrict__ h1s,
                               const float* __restrict__ b1, const float* __restrict__ W2,
                               __half* __restrict__ h2s, int N) {
    __shared__ __align__(16) float Ws[HID * OUT];
    __shared__ __align__(16) float Hs[L2_NODES * HS];
    __shared__ float Dis[L2_NODES];
    int t = threadIdx.x;
    int warp = t >> 5, lane = t & 31;
    int nodeBase = blockIdx.x * L2_NODES;

    for (int i = t; i < HID * OUT / 4; i += 256)
        ((float4*)Ws)[i] = ((const float4*)W2)[i];

    float2 bb;
    bb.x = b1[lane * 2];
    bb.y = b1[lane * 2 + 1];

    #pragma unroll 1
    for (int j = 0; j < 8; j++) {
        int n  = warp * 8 + j;
        int gn = nodeBase + n;
        float2 acc = make_float2(0.f, 0.f);
        float d = 0.f;
        if (gn < N) {
            d = g_dis[gn];
            int beg = g_offs[gn], end = g_offs[gn + 1];
            for (int e = beg; e < end; e += 32) {
                int cnt = min(32, end - e);
                int s = (lane < cnt) ? g_csr[e + lane] : 0;
                int k = 0;
                for (; k + 8 <= cnt; k += 8) {
                    float2 v[8];
                    #pragma unroll
                    for (int u = 0; u < 8; u++) {
                        int ss = __shfl_sync(0xffffffffu, s, k + u);
                        v[u] = __half22float2(__ldg((const __half2*)(h1s + (size_t)ss * HID + lane * 2)));
                    }
                    float2 t0, t1, t2, t3;
                    t0.x = v[0].x + v[1].x; t0.y = v[0].y + v[1].y;
                    t1.x = v[2].x + v[3].x; t1.y = v[2].y + v[3].y;
                    t2.x = v[4].x + v[5].x; t2.y = v[4].y + v[5].y;
                    t3.x = v[6].x + v[7].x; t3.y = v[6].y + v[7].y;
                    acc.x += (t0.x + t1.x) + (t2.x + t3.x);
                    acc.y += (t0.y + t1.y) + (t2.y + t3.y);
                }
                for (; k < cnt; k++) {
                    int ss = __shfl_sync(0xffffffffu, s, k);
                    float2 v = __half22float2(__ldg((const __half2*)(h1s + (size_t)ss * HID + lane * 2)));
                    acc.x += v.x; acc.y += v.y;
                }
            }
            // self loop
            float2 sv = __half22float2(*(const __half2*)(h1s + (size_t)gn * HID + lane * 2));
            acc.x += sv.x; acc.y += sv.y;
            acc.x = fmaxf(fmaf(d, acc.x, bb.x), 0.f);
            acc.y = fmaxf(fmaf(d, acc.y, bb.y), 0.f);
        }
        *(float2*)(Hs + n * HS + lane * 2) = acc;
        if (lane == 0) Dis[n] = d;
    }
    __syncthreads();

    // GEMM: 64x32 = Hs(64x64) @ Ws(64x32); thread = 2 nodes x 4 ch, f32x2 packed
    int ch0 = (t & 7) * 4;
    int n0  = (t >> 3) * 2;
    unsigned long long a01[2] = {0ull, 0ull};
    unsigned long long a23[2] = {0ull, 0ull};
    #pragma unroll 4
    for (int k = 0; k < HID; k += 4) {
        float4 xv[2];
        #pragma unroll
        for (int j = 0; j < 2; j++) xv[j] = *(float4*)(Hs + (n0 + j) * HS + k);
        #pragma unroll
        for (int kk = 0; kk < 4; kk++) {
            ulonglong2 wv = *(const ulonglong2*)(Ws + (k + kk) * OUT + ch0);
            #pragma unroll
            for (int j = 0; j < 2; j++) {
                float xs = (kk == 0) ? xv[j].x : (kk == 1) ? xv[j].y : (kk == 2) ? xv[j].z : xv[j].w;
                unsigned long long xx = pack2(xs);
                a01[j] = fma2(xx, wv.x, a01[j]);
                a23[j] = fma2(xx, wv.y, a23[j]);
            }
        }
    }
    #pragma unroll
    for (int j = 0; j < 2; j++) {
        int gn = nodeBase + n0 + j;
        if (gn < N) {
            float d = Dis[n0 + j];
            __half2 o0 = __floats2half2_rn(lo32(a01[j]) * d, hi32(a01[j]) * d);
            __half2 o1 = __floats2half2_rn(lo32(a23[j]) * d, hi32(a23[j]) * d);
            *(__half2*)(h2s + (size_t)gn * OUT + ch0)     = o0;
            *(__half2*)(h2s + (size_t)gn * OUT + ch0 + 2) = o1;
        }
    }
}

// ---------------------------------------------------------------- fused agg2 + scale + bias -> out
__global__ void agg2_final_kernel(const __half* __restrict__ h2s,
                                  const float* __restrict__ b2,
                                  float* __restrict__ out, int N) {
    int w = (blockIdx.x * blockDim.x + threadIdx.x) >> 5;
    int lane = threadIdx.x & 31;
    if (w >= N) return;
    float acc = 0.f;
    int beg = g_offs[w], end = g_offs[w + 1];
    for (int e = beg; e < end; e += 32) {
        int cnt = min(32, end - e);
        int s = (lane < cnt) ? g_csr[e + lane] : 0;
        int k = 0;
        for (; k + 8 <= cnt; k += 8) {
            float v[8];
            #pragma unroll
            for (int u = 0; u < 8; u++) {
                int ss = __shfl_sync(0xffffffffu, s, k + u);
                v[u] = __half2float(__ldg(h2s + (size_t)ss * OUT + lane));
            }
            acc += ((v[0] + v[1]) + (v[2] + v[3])) + ((v[4] + v[5]) + (v[6] + v[7]));
        }
        for (; k < cnt; k++) {
            int ss = __shfl_sync(0xffffffffu, s, k);
            acc += __half2float(__ldg(h2s + (size_t)ss * OUT + lane));
        }
    }
    acc += __half2float(h2s[(size_t)w * OUT + lane]);   // self loop
    out[(size_t)w * OUT + lane] = fmaf(g_dis[w], acc, b2[lane]);
}

// ---------------------------------------------------------------- launch
extern "C" void kernel_launch(void* const* d_in, const int* in_sizes, int n_in,
                              void* d_out, int out_size) {
    const float* x  = (const float*)d_in[0];
    const int*   ei = (const int*)d_in[1];
    const float* W1 = (const float*)d_in[2];
    const float* b1 = (const float*)d_in[3];
    const float* W2 = (const float*)d_in[4];
    const float* b2 = (const float*)d_in[5];
    float* out = (float*)d_out;

    int N = in_sizes[0] / IN_CH;
    int E = in_sizes[1] / 2;

    __half *h1s, *h2s;
    int* cnt_ptr;
    cudaGetSymbolAddress((void**)&h1s, g_h1s);
    cudaGetSymbolAddress((void**)&h2s, g_h2s);
    cudaGetSymbolAddress((void**)&cnt_ptr, g_cnt);

    const int gemm1_smem = (IN_CH * HID + G1_NODES * XS) * (int)sizeof(float);

    // one-time host-side resources (created on first, uncaptured, correctness call)
    static cudaStream_t s2 = nullptr;
    static cudaEvent_t evF = nullptr, evJ = nullptr;
    if (s2 == nullptr) {
        cudaStreamCreateWithFlags(&s2, cudaStreamNonBlocking);
        cudaEventCreateWithFlags(&evF, cudaEventDisableTiming);
        cudaEventCreateWithFlags(&evJ, cudaEventDisableTiming);
        cudaFuncSetAttribute(gemm1_kernel, cudaFuncAttributeMaxDynamicSharedMemorySize, gemm1_smem);
    }

    int B = (N + SCAN_B - 1) / SCAN_B;
    int E4 = (E + 3) / 4;

    // fork: gemm1 (depends on nothing graph-related) on side stream
    cudaEventRecord(evF, 0);
    cudaStreamWaitEvent(s2, evF, 0);
    gemm1_kernel<<<(N + G1_NODES - 1) / G1_NODES, 256, gemm1_smem, s2>>>(x, W1, h1s, N);
    cudaEventRecord(evJ, s2);

    // main: CSR build (vectorized count/scatter)
    cudaMemsetAsync(cnt_ptr, 0, (size_t)N * sizeof(int), 0);
    count_kernel<<<(E4 + 255) / 256, 256>>>(ei, E);
    scan1_kernel<<<B, SCAN_B>>>(N);
    scan23_kernel<<<B, SCAN_B>>>(N, E);
    scatter_kernel<<<(E4 + 255) / 256, 256>>>(ei, E);

    // join: scale needs h1s (side) + dis (main)
    cudaStreamWaitEvent(0, evJ, 0);
    scale_h1_kernel<<<(N * (HID / 8) + 255) / 256, 256>>>(h1s, N);
    layer12_kernel<<<(N + L2_NODES - 1) / L2_NODES, 256>>>(h1s, b1, W2, h2s, N);
    agg2_final_kernel<<<(N * 32 + 255) / 256, 256>>>(h2s, b2, out, N);
}